// round 3
// baseline (speedup 1.0000x reference)
#include <cuda_runtime.h>
#include <cuda_bf16.h>
#include <stdint.h>

#define L 4096

// Normalized int32 copy of seq_ids (handles both int64 and int32 input encodings).
__device__ int g_seq32[L];

__global__ void normalize_seq_kernel(const int* __restrict__ raw) {
    __shared__ int is64;
    if (threadIdx.x == 0) {
        const long long* p = reinterpret_cast<const long long*>(raw);
        int ok = 1;
        #pragma unroll
        for (int k = 0; k < 16; k++) {
            long long v = p[k];
            if (v < 0 || v > 3) { ok = 0; break; }
        }
        is64 = ok;
    }
    __syncthreads();
    const long long* p64 = reinterpret_cast<const long long*>(raw);
    for (int idx = threadIdx.x; idx < L; idx += blockDim.x) {
        g_seq32[idx] = is64 ? (int)p64[idx] : raw[idx];
    }
}

// One block per output row (c, i). 32768 blocks, 256 threads, 4 float4 stores/thread.
//   c = blockIdx >> 12 in [0,8), i = blockIdx & 4095.
//   c in [0,4): row is broadcast of (seq[i]==c)   — compare once, 4 identical STG.128
//   c in [4,8): row is one-hot of seq[j] vs (c-4) — 4x (LDG.128 + compare + STG.128), MLP=4
__global__ void __launch_bounds__(256) seq_embed_row_kernel(float4* __restrict__ out) {
    unsigned int b = blockIdx.x;
    unsigned int c = b >> 12;        // channel 0..7
    unsigned int i = b & 4095u;      // row index
    float4* rowp = out + (size_t)b * 1024u;   // 1024 float4 = 16 KB per row
    unsigned int tx = threadIdx.x;

    if (c < 4u) {
        float x = (g_seq32[i] == (int)c) ? 1.0f : 0.0f;
        float4 v = {x, x, x, x};
        #pragma unroll
        for (int k = 0; k < 4; k++)
            __stcs(rowp + tx + k * 256u, v);
    } else {
        int cc = (int)c - 4;
        const int4* s4 = reinterpret_cast<const int4*>(g_seq32);
        #pragma unroll
        for (int k = 0; k < 4; k++) {
            unsigned int j4 = tx + k * 256u;
            int4 s = s4[j4];
            float4 v;
            v.x = (s.x == cc) ? 1.0f : 0.0f;
            v.y = (s.y == cc) ? 1.0f : 0.0f;
            v.z = (s.z == cc) ? 1.0f : 0.0f;
            v.w = (s.w == cc) ? 1.0f : 0.0f;
            __stcs(rowp + j4, v);
        }
    }
}

extern "C" void kernel_launch(void* const* d_in, const int* in_sizes, int n_in,
                              void* d_out, int out_size) {
    const int* raw_seq = (const int*)d_in[0];   // seq_ids (int64 or int32, auto-detected)
    // d_in[1] is base_table (identity eye(4)) — comparisons suffice.

    normalize_seq_kernel<<<1, 256>>>(raw_seq);

    // 8 channels * 4096 rows = 32768 blocks, one 16 KB row each.
    seq_embed_row_kernel<<<8 * L, 256>>>((float4*)d_out);
}

// round 4
// speedup vs baseline: 1.0270x; 1.0270x over previous
#include <cuda_runtime.h>
#include <cuda_bf16.h>
#include <stdint.h>

#define L 4096

// Single fused kernel: one block per output row (c, i), reading raw ids directly.
//   b = blockIdx.x in [0, 32768):  c = b >> 12 (channel 0..7), i = b & 4095.
//   c in [0,4): row = broadcast of (seq[i]==c)      — 1 id load, 4x STG.128
//   c in [4,8): row = one-hot of seq[j] vs (c-4)    — 4x (32B id load + cmp + STG.128)
//
// Input width (int64 vs int32) is detected per block by thread 0: the first 16
// words reinterpreted as int64 are all in [0,3] iff the data is int64
// (false-positive prob ~ 2^-32 for random int32 ids). All loads hit L2 after
// the first wave; extra read traffic ~4 MB vs 512 MB of writes.
__global__ void __launch_bounds__(256) seq_embed_fused_kernel(
        const int* __restrict__ raw, float4* __restrict__ out) {
    __shared__ int s_is64;
    unsigned int b = blockIdx.x;
    unsigned int c = b >> 12;        // channel 0..7
    unsigned int i = b & 4095u;      // row index
    unsigned int tx = threadIdx.x;

    if (tx == 0) {
        const long long* p = reinterpret_cast<const long long*>(raw);
        int ok = 1;
        #pragma unroll
        for (int k = 0; k < 16; k++) {
            long long v = p[k];
            ok &= (v >= 0 && v <= 3);
        }
        s_is64 = ok;
    }
    __syncthreads();
    const int is64 = s_is64;

    float4* rowp = out + (size_t)b * 1024u;   // 1024 float4 = 16 KB per row

    if (c < 4u) {
        long long vi = is64 ? reinterpret_cast<const long long*>(raw)[i]
                            : (long long)raw[i];
        float x = (vi == (long long)c) ? 1.0f : 0.0f;
        float4 v = {x, x, x, x};
        #pragma unroll
        for (int k = 0; k < 4; k++)
            __stcs(rowp + tx + k * 256u, v);
    } else {
        int cc = (int)c - 4;
        const int4* p4 = reinterpret_cast<const int4*>(raw);
        #pragma unroll
        for (int k = 0; k < 4; k++) {
            unsigned int j4 = tx + k * 256u;   // quad index: ids 4*j4 .. 4*j4+3
            int v0, v1, v2, v3;
            if (is64) {
                // int64 layout: 4 ids = 32 B = two int4; even words are the values
                int4 a = p4[2 * j4];
                int4 d = p4[2 * j4 + 1];
                v0 = a.x; v1 = a.z; v2 = d.x; v3 = d.z;
            } else {
                int4 a = p4[j4];
                v0 = a.x; v1 = a.y; v2 = a.z; v3 = a.w;
            }
            float4 v;
            v.x = (v0 == cc) ? 1.0f : 0.0f;
            v.y = (v1 == cc) ? 1.0f : 0.0f;
            v.z = (v2 == cc) ? 1.0f : 0.0f;
            v.w = (v3 == cc) ? 1.0f : 0.0f;
            __stcs(rowp + j4, v);
        }
    }
}

extern "C" void kernel_launch(void* const* d_in, const int* in_sizes, int n_in,
                              void* d_out, int out_size) {
    const int* raw_seq = (const int*)d_in[0];   // seq_ids (int64 or int32, auto-detected)
    // d_in[1] is base_table (identity eye(4)) — comparisons suffice.

    // 8 channels * 4096 rows = 32768 blocks, one 16 KB row each.
    seq_embed_fused_kernel<<<8 * L, 256>>>(raw_seq, (float4*)d_out);
}